// round 1
// baseline (speedup 1.0000x reference)
#include <cuda_runtime.h>
#include <math.h>

constexpr int BATCH = 4;
constexpr int SEQ   = 4096;
constexpr int CH    = 256;
constexpr int ROWS  = BATCH * SEQ; // 16384

// ---- device scratch (no allocations allowed) ----
__device__ float g_q[(size_t)BATCH * SEQ * CH];
__device__ float g_k[(size_t)BATCH * SEQ * CH];
__device__ float g_v[(size_t)BATCH * SEQ * CH];
__device__ float g_o[(size_t)BATCH * SEQ * CH];
__device__ float g_S[(size_t)BATCH * SEQ * SEQ];   // 268 MB logits -> probabilities (in place)
__device__ float g_c[ROWS];     // (1/16)/sqrt(var+eps) per row
__device__ float g_mc[ROWS];    // mu * c per row
__device__ float g_invZ[ROWS];  // 1/sum(exp) per row

// ============================================================================
// NT GEMM body (K = 256, lda = ldb = 256):
//   C[row0:+128, col0:+128] = (A (+A2)) * B^T  (+ bias)
// A: [*,256] row-major (K contiguous), B: [*,256] row-major (K contiguous).
// 256 threads, 128x128 tile, BK=8, 8x8 per thread.
// ============================================================================
template <bool ADD_A2, bool HAS_BIAS>
__device__ __forceinline__ void gemm_nt_128x128_k256(
    const float* __restrict__ A, const float* __restrict__ A2,
    const float* __restrict__ B, float* __restrict__ C,
    int row0, int col0, int ldc, const float* __restrict__ bias)
{
    __shared__ float As[8][128];
    __shared__ float Bs[8][128];

    const int tid = threadIdx.x;
    const int lr  = tid >> 1;          // 0..127
    const int lk  = (tid & 1) << 2;    // 0 or 4
    const int tx  = tid & 15;          // 0..15
    const int ty  = tid >> 4;          // 0..15

    float acc[8][8];
#pragma unroll
    for (int i = 0; i < 8; ++i)
#pragma unroll
        for (int j = 0; j < 8; ++j) acc[i][j] = 0.f;

    const float* Ap  = A + (size_t)(row0 + lr) * CH + lk;
    const float* A2p = ADD_A2 ? (A2 + (size_t)(row0 + lr) * CH + lk) : nullptr;
    const float* Bp  = B + (size_t)(col0 + lr) * CH + lk;

    for (int k0 = 0; k0 < CH; k0 += 8) {
        float4 av = *(const float4*)(Ap + k0);
        if (ADD_A2) {
            float4 a2 = *(const float4*)(A2p + k0);
            av.x += a2.x; av.y += a2.y; av.z += a2.z; av.w += a2.w;
        }
        float4 bv = *(const float4*)(Bp + k0);
        __syncthreads();
        As[lk + 0][lr] = av.x; As[lk + 1][lr] = av.y;
        As[lk + 2][lr] = av.z; As[lk + 3][lr] = av.w;
        Bs[lk + 0][lr] = bv.x; Bs[lk + 1][lr] = bv.y;
        Bs[lk + 2][lr] = bv.z; Bs[lk + 3][lr] = bv.w;
        __syncthreads();
#pragma unroll
        for (int kk = 0; kk < 8; ++kk) {
            float a[8], b[8];
            *(float4*)&a[0] = *(const float4*)&As[kk][ty * 8];
            *(float4*)&a[4] = *(const float4*)&As[kk][ty * 8 + 4];
            *(float4*)&b[0] = *(const float4*)&Bs[kk][tx * 8];
            *(float4*)&b[4] = *(const float4*)&Bs[kk][tx * 8 + 4];
#pragma unroll
            for (int i = 0; i < 8; ++i)
#pragma unroll
                for (int j = 0; j < 8; ++j)
                    acc[i][j] = fmaf(a[i], b[j], acc[i][j]);
        }
    }

#pragma unroll
    for (int i = 0; i < 8; ++i) {
        const int r = row0 + ty * 8 + i;
#pragma unroll
        for (int j = 0; j < 8; j += 4) {
            const int cidx = col0 + tx * 8 + j;
            float4 o = make_float4(acc[i][j], acc[i][j + 1], acc[i][j + 2], acc[i][j + 3]);
            if (HAS_BIAS) {
                o.x += bias[cidx + 0]; o.y += bias[cidx + 1];
                o.z += bias[cidx + 2]; o.w += bias[cidx + 3];
            }
            *(float4*)(C + (size_t)r * ldc + cidx) = o;
        }
    }
}

// ---- K1: q/k/v projections (z selects which) ----
__global__ __launch_bounds__(256) void proj_kernel(
    const float* __restrict__ q, const float* __restrict__ k, const float* __restrict__ v,
    const float* __restrict__ Wq, const float* __restrict__ bq,
    const float* __restrict__ Wk, const float* __restrict__ bk,
    const float* __restrict__ Wv, const float* __restrict__ bv)
{
    const float *X, *W, *bias;
    float* Y;
    if (blockIdx.z == 0)      { X = q; W = Wq; bias = bq; Y = g_q; }
    else if (blockIdx.z == 1) { X = k; W = Wk; bias = bk; Y = g_k; }
    else                      { X = v; W = Wv; bias = bv; Y = g_v; }
    gemm_nt_128x128_k256<false, true>(X, nullptr, W, Y,
                                      blockIdx.y * 128, blockIdx.x * 128, CH, bias);
}

// ---- K2: S = q @ k^T per batch ----
__global__ __launch_bounds__(256) void qk_kernel()
{
    const int b = blockIdx.z;
    const float* A  = g_q + (size_t)b * SEQ * CH;
    const float* B  = g_k + (size_t)b * SEQ * CH;
    float*       Sp = g_S + (size_t)b * SEQ * SEQ;
    gemm_nt_128x128_k256<false, false>(A, nullptr, B, Sp,
                                       blockIdx.y * 128, blockIdx.x * 128, SEQ, nullptr);
}

// ---- K3: per-row sum / sumsq -> c = (1/16)*rsqrt(var+eps), mc = mu*c ----
__global__ __launch_bounds__(256) void stats_kernel()
{
    const int row = blockIdx.x;
    const float4* s = (const float4*)(g_S + (size_t)row * SEQ);
    const int tid = threadIdx.x;
    float sum = 0.f, ss = 0.f;
#pragma unroll
    for (int i = tid; i < SEQ / 4; i += 256) {
        float4 x = s[i];
        sum += x.x + x.y + x.z + x.w;
        ss  += x.x * x.x + x.y * x.y + x.z * x.z + x.w * x.w;
    }
    __shared__ float s1[256], s2[256];
    s1[tid] = sum; s2[tid] = ss;
    __syncthreads();
    for (int off = 128; off > 0; off >>= 1) {
        if (tid < off) { s1[tid] += s1[tid + off]; s2[tid] += s2[tid + off]; }
        __syncthreads();
    }
    if (tid == 0) {
        float mu  = s1[0] * (1.f / SEQ);
        float var = s2[0] * (1.f / SEQ) - mu * mu;
        float cc  = rsqrtf(var + 1e-5f) * 0.0625f;   // * EMBED_DIM^-0.5
        g_c[row]  = cc;
        g_mc[row] = mu * cc;
    }
}

// ---- K4: S <- exp(S*c - mc) in place; Z per row (shift-invariant softmax) ----
__global__ __launch_bounds__(256) void expz_kernel()
{
    const int row = blockIdx.x;
    float4* s = (float4*)(g_S + (size_t)row * SEQ);
    const int tid = threadIdx.x;
    const float cc = g_c[row], mcc = g_mc[row];
    float z = 0.f;
#pragma unroll
    for (int i = tid; i < SEQ / 4; i += 256) {
        float4 x = s[i];
        x.x = __expf(fmaf(x.x, cc, -mcc));
        x.y = __expf(fmaf(x.y, cc, -mcc));
        x.z = __expf(fmaf(x.z, cc, -mcc));
        x.w = __expf(fmaf(x.w, cc, -mcc));
        s[i] = x;
        z += x.x + x.y + x.z + x.w;
    }
    __shared__ float s1[256];
    s1[tid] = z;
    __syncthreads();
    for (int off = 128; off > 0; off >>= 1) {
        if (tid < off) s1[tid] += s1[tid + off];
        __syncthreads();
    }
    if (tid == 0) g_invZ[row] = 1.f / s1[0];
}

// ---- K5: O = (P @ V) * invZ per batch (NN GEMM, K = 4096) ----
__global__ __launch_bounds__(256) void pv_kernel()
{
    const int b = blockIdx.z;
    const float* __restrict__ P = g_S + (size_t)b * SEQ * SEQ;
    const float* __restrict__ V = g_v + (size_t)b * SEQ * CH;
    float* __restrict__ O = g_o + (size_t)b * SEQ * CH;
    const int row0 = blockIdx.y * 128;
    const int col0 = blockIdx.x * 128;

    __shared__ float As[8][128];
    __shared__ float Bs[8][128];

    const int tid = threadIdx.x;
    const int lr  = tid >> 1;
    const int lk  = (tid & 1) << 2;
    const int kr  = tid >> 5;          // 0..7
    const int nc  = (tid & 31) << 2;   // 0..124
    const int tx  = tid & 15;
    const int ty  = tid >> 4;

    float acc[8][8];
#pragma unroll
    for (int i = 0; i < 8; ++i)
#pragma unroll
        for (int j = 0; j < 8; ++j) acc[i][j] = 0.f;

    const float* Pp = P + (size_t)(row0 + lr) * SEQ + lk;
    const float* Vp = V + (size_t)kr * CH + col0 + nc;

    for (int k0 = 0; k0 < SEQ; k0 += 8) {
        float4 av = *(const float4*)(Pp + k0);
        float4 bv = *(const float4*)(Vp + (size_t)k0 * CH);
        __syncthreads();
        As[lk + 0][lr] = av.x; As[lk + 1][lr] = av.y;
        As[lk + 2][lr] = av.z; As[lk + 3][lr] = av.w;
        *(float4*)&Bs[kr][nc] = bv;
        __syncthreads();
#pragma unroll
        for (int kk = 0; kk < 8; ++kk) {
            float a[8], bb[8];
            *(float4*)&a[0]  = *(const float4*)&As[kk][ty * 8];
            *(float4*)&a[4]  = *(const float4*)&As[kk][ty * 8 + 4];
            *(float4*)&bb[0] = *(const float4*)&Bs[kk][tx * 8];
            *(float4*)&bb[4] = *(const float4*)&Bs[kk][tx * 8 + 4];
#pragma unroll
            for (int i = 0; i < 8; ++i)
#pragma unroll
                for (int j = 0; j < 8; ++j)
                    acc[i][j] = fmaf(a[i], bb[j], acc[i][j]);
        }
    }

    const int rz = b * SEQ + row0 + ty * 8;
#pragma unroll
    for (int i = 0; i < 8; ++i) {
        const float iz = g_invZ[rz + i];
        const int r = row0 + ty * 8 + i;
#pragma unroll
        for (int j = 0; j < 8; j += 4) {
            const int cidx = col0 + tx * 8 + j;
            float4 o = make_float4(acc[i][j] * iz, acc[i][j + 1] * iz,
                                   acc[i][j + 2] * iz, acc[i][j + 3] * iz);
            *(float4*)(O + (size_t)r * CH + cidx) = o;
        }
    }
}

// ---- K6: out = (query + O) @ Wm^T + bm ----
__global__ __launch_bounds__(256) void final_kernel(
    const float* __restrict__ query, const float* __restrict__ Wm,
    const float* __restrict__ bm, float* __restrict__ out)
{
    gemm_nt_128x128_k256<true, true>(query, g_o, Wm, out,
                                     blockIdx.y * 128, blockIdx.x * 128, CH, bm);
}

extern "C" void kernel_launch(void* const* d_in, const int* in_sizes, int n_in,
                              void* d_out, int out_size)
{
    const float* query = (const float*)d_in[0];
    const float* key   = (const float*)d_in[1];
    const float* value = (const float*)d_in[2];
    const float* Wq    = (const float*)d_in[3];
    const float* bq    = (const float*)d_in[4];
    const float* Wk    = (const float*)d_in[5];
    const float* bk    = (const float*)d_in[6];
    const float* Wv    = (const float*)d_in[7];
    const float* bv    = (const float*)d_in[8];
    const float* Wm    = (const float*)d_in[9];
    const float* bm    = (const float*)d_in[10];
    float* out = (float*)d_out;

    proj_kernel<<<dim3(CH / 128, ROWS / 128, 3), 256>>>(query, key, value,
                                                        Wq, bq, Wk, bk, Wv, bv);
    qk_kernel<<<dim3(SEQ / 128, SEQ / 128, BATCH), 256>>>();
    stats_kernel<<<ROWS, 256>>>();
    expz_kernel<<<ROWS, 256>>>();
    pv_kernel<<<dim3(CH / 128, SEQ / 128, BATCH), 256>>>();
    final_kernel<<<dim3(CH / 128, ROWS / 128), 256>>>(query, Wm, bm, out);
}

// round 3
// speedup vs baseline: 4.9917x; 4.9917x over previous
#include <cuda_runtime.h>
#include <cuda_bf16.h>
#include <math.h>
#include <cstdint>

constexpr int BATCH = 4;
constexpr int SEQ   = 4096;
constexpr int CH    = 256;
constexpr int ROWS  = BATCH * SEQ; // 16384

// ---- device scratch ----
__device__ __nv_bfloat16 g_qh[(size_t)ROWS * CH];
__device__ __nv_bfloat16 g_kh[(size_t)ROWS * CH];
__device__ __nv_bfloat16 g_vh[(size_t)ROWS * CH];
__device__ __nv_bfloat16 g_vt[(size_t)BATCH * CH * SEQ];   // V^T per batch: [c][m]
__device__ float         g_o [(size_t)ROWS * CH];
__device__ __nv_bfloat16 g_Sh[(size_t)BATCH * SEQ * SEQ];  // logits -> probs in place (bf16)
__device__ float         g_invZ[ROWS];

// ======================= helpers =======================
__device__ __forceinline__ uint32_t smem_u32(const void* p) {
    uint32_t a;
    asm("{ .reg .u64 t; cvta.to.shared.u64 t, %1; cvt.u32.u64 %0, t; }" : "=r"(a) : "l"(p));
    return a;
}
__device__ __forceinline__ uint32_t pack_bf2(float a, float b) {
    __nv_bfloat162 h = __floats2bfloat162_rn(a, b);
    return *(uint32_t*)&h;
}
__device__ __forceinline__ void ldm_x4(uint32_t (&r)[4], uint32_t addr) {
    asm volatile("ldmatrix.sync.aligned.m8n8.x4.shared.b16 {%0,%1,%2,%3}, [%4];"
        : "=r"(r[0]), "=r"(r[1]), "=r"(r[2]), "=r"(r[3]) : "r"(addr));
}
__device__ __forceinline__ void mma_bf16(float (&d)[4], const uint32_t (&a)[4],
                                         uint32_t b0, uint32_t b1) {
    asm volatile("mma.sync.aligned.m16n8k16.row.col.f32.bf16.bf16.f32 "
        "{%0,%1,%2,%3}, {%4,%5,%6,%7}, {%8,%9}, {%0,%1,%2,%3};"
        : "+f"(d[0]), "+f"(d[1]), "+f"(d[2]), "+f"(d[3])
        : "r"(a[0]), "r"(a[1]), "r"(a[2]), "r"(a[3]), "r"(b0), "r"(b1));
}

#define CP_ASYNC16(dst, src) asm volatile("cp.async.cg.shared.global [%0], [%1], 16;" :: "r"(dst), "l"(src) : "memory")
#define CP_COMMIT()          asm volatile("cp.async.commit_group;" ::: "memory")
#define CP_WAIT(n)           asm volatile("cp.async.wait_group %0;" :: "n"(n) : "memory")

// One k16 MMA step for a 32x64 warp tile from padded smem.
// LDB = smem row stride in BYTES. sa/sb point at tile base (byte smem addrs).
template <int LDB>
__device__ __forceinline__ void mma_step(uint32_t sa, uint32_t sb, int kb,
                                         int m0b, int n0b, int lane,
                                         float (&acc)[2][8][4])
{
    uint32_t a[2][4];
#pragma unroll
    for (int i = 0; i < 2; ++i)
        ldm_x4(a[i], sa + (uint32_t)(m0b + i * 16 + (lane & 15)) * LDB + kb + ((lane >> 4) << 4));
    uint32_t bb[4][4];
#pragma unroll
    for (int p = 0; p < 4; ++p)
        ldm_x4(bb[p], sb + (uint32_t)(n0b + p * 16 + ((lane >> 4) << 3) + (lane & 7)) * LDB
                      + kb + (((lane >> 3) & 1) << 4));
#pragma unroll
    for (int i = 0; i < 2; ++i)
#pragma unroll
        for (int j = 0; j < 8; ++j)
            mma_bf16(acc[i][j], a[i], bb[j >> 1][(j & 1) * 2], bb[j >> 1][(j & 1) * 2 + 1]);
}

// strides
constexpr int LD1 = 528;            // 256 bf16 + 8 pad = 264 elems -> 528 bytes
constexpr int DS1 = 2 * 128 * LD1;  // 135168 (A + B tiles, K=256 one-shot)
constexpr int LD2 = 144;            // 64 bf16 + 8 pad = 72 elems -> 144 bytes
constexpr int STG = 128 * LD2;      // 18432 per stage
constexpr int DS2 = 4 * STG;        // 73728 (A,B double-buffered)

// ======================= K1: projections (bf16 HMMA, K=256 one-shot) =======================
__global__ __launch_bounds__(256) void proj_mma_kernel(
    const float* __restrict__ q, const float* __restrict__ k, const float* __restrict__ v,
    const float* __restrict__ Wq, const float* __restrict__ bq,
    const float* __restrict__ Wk, const float* __restrict__ bk,
    const float* __restrict__ Wv, const float* __restrict__ bv)
{
    extern __shared__ __align__(16) char sm[];
    const uint32_t base = smem_u32(sm);
    const int tid = threadIdx.x, lane = tid & 31, wid = tid >> 5;
    const int row0 = blockIdx.y * 128, col0 = blockIdx.x * 128;
    const int m0b = (wid & 3) * 32, n0b = (wid >> 2) * 64;

    const float *X, *W, *bias; __nv_bfloat16* Y;
    if (blockIdx.z == 0)      { X = q; W = Wq; bias = bq; Y = g_qh; }
    else if (blockIdx.z == 1) { X = k; W = Wk; bias = bk; Y = g_kh; }
    else                      { X = v; W = Wv; bias = bv; Y = g_vh; }

    // fp32 -> bf16 into padded smem: A rows = X[row0+*], B rows = W[col0+*]
#pragma unroll
    for (int j = 0; j < 16; ++j) {
        int idx = tid + 256 * j;
        int r = idx >> 5, s = idx & 31;
        const float* xa = X + (size_t)(row0 + r) * CH + s * 8;
        float4 x0 = *(const float4*)xa, x1 = *(const float4*)(xa + 4);
        uint4 av = make_uint4(pack_bf2(x0.x, x0.y), pack_bf2(x0.z, x0.w),
                              pack_bf2(x1.x, x1.y), pack_bf2(x1.z, x1.w));
        *(uint4*)(sm + (size_t)r * LD1 + s * 16) = av;
        const float* wa = W + (size_t)(col0 + r) * CH + s * 8;
        float4 w0 = *(const float4*)wa, w1 = *(const float4*)(wa + 4);
        uint4 bv2 = make_uint4(pack_bf2(w0.x, w0.y), pack_bf2(w0.z, w0.w),
                               pack_bf2(w1.x, w1.y), pack_bf2(w1.z, w1.w));
        *(uint4*)(sm + 128 * LD1 + (size_t)r * LD1 + s * 16) = bv2;
    }
    __syncthreads();

    float acc[2][8][4];
#pragma unroll
    for (int i = 0; i < 2; ++i)
#pragma unroll
        for (int j = 0; j < 8; ++j)
#pragma unroll
            for (int t = 0; t < 4; ++t) acc[i][j][t] = 0.f;

#pragma unroll
    for (int ks = 0; ks < 16; ++ks)
        mma_step<LD1>(base, base + 128 * LD1, ks * 32, m0b, n0b, lane, acc);

    // epilogue: +bias, bf16 store
#pragma unroll
    for (int i = 0; i < 2; ++i) {
        const int r = row0 + m0b + i * 16 + (lane >> 2);
#pragma unroll
        for (int j = 0; j < 8; ++j) {
            const int c = col0 + n0b + j * 8 + (lane & 3) * 2;
            float2 bv2 = *(const float2*)(bias + c);
            *(uint32_t*)(Y + (size_t)r * CH + c) =
                pack_bf2(acc[i][j][0] + bv2.x, acc[i][j][1] + bv2.y);
            *(uint32_t*)(Y + (size_t)(r + 8) * CH + c) =
                pack_bf2(acc[i][j][2] + bv2.x, acc[i][j][3] + bv2.y);
        }
    }
}

// ======================= K2: V transpose (bf16) =======================
__global__ __launch_bounds__(256) void vt_kernel()
{
    __shared__ __nv_bfloat16 t[64][72];
    const int b = blockIdx.z, m0 = blockIdx.x * 64, c0 = blockIdx.y * 64;
    const __nv_bfloat16* src = g_vh + ((size_t)b * SEQ + m0) * CH + c0;
#pragma unroll
    for (int j = 0; j < 2; ++j) {
        int idx = threadIdx.x + 256 * j;
        int r = idx >> 3, cu = idx & 7;
        *(uint4*)&t[r][cu * 8] = *(const uint4*)(src + (size_t)r * CH + cu * 8);
    }
    __syncthreads();
    __nv_bfloat16* dst = g_vt + ((size_t)b * CH + c0) * SEQ + m0;
#pragma unroll
    for (int j = 0; j < 2; ++j) {
        int idx = threadIdx.x + 256 * j;
        int c = idx >> 3, mu = idx & 7;
        __nv_bfloat16 tmp[8];
#pragma unroll
        for (int i = 0; i < 8; ++i) tmp[i] = t[mu * 8 + i][c];
        *(uint4*)(dst + (size_t)c * SEQ + mu * 8) = *(uint4*)tmp;
    }
}

// ======================= K3: S = q k^T (bf16 HMMA, K=256 one-shot) =======================
__global__ __launch_bounds__(256) void qk_mma_kernel()
{
    extern __shared__ __align__(16) char sm[];
    const uint32_t base = smem_u32(sm);
    const int tid = threadIdx.x, lane = tid & 31, wid = tid >> 5;
    const int b = blockIdx.z, row0 = blockIdx.y * 128, col0 = blockIdx.x * 128;
    const int m0b = (wid & 3) * 32, n0b = (wid >> 2) * 64;

    const __nv_bfloat16* A = g_qh + ((size_t)b * SEQ + row0) * CH;
    const __nv_bfloat16* B = g_kh + ((size_t)b * SEQ + col0) * CH;
#pragma unroll
    for (int j = 0; j < 16; ++j) {
        int idx = tid + 256 * j;
        int r = idx >> 5, s = idx & 31;
        *(uint4*)(sm + (size_t)r * LD1 + s * 16)             = *(const uint4*)(A + (size_t)r * CH + s * 8);
        *(uint4*)(sm + 128 * LD1 + (size_t)r * LD1 + s * 16) = *(const uint4*)(B + (size_t)r * CH + s * 8);
    }
    __syncthreads();

    float acc[2][8][4];
#pragma unroll
    for (int i = 0; i < 2; ++i)
#pragma unroll
        for (int j = 0; j < 8; ++j)
#pragma unroll
            for (int t = 0; t < 4; ++t) acc[i][j][t] = 0.f;

#pragma unroll
    for (int ks = 0; ks < 16; ++ks)
        mma_step<LD1>(base, base + 128 * LD1, ks * 32, m0b, n0b, lane, acc);

    // stage C (bf16) through smem for coalesced global writes
    __syncthreads();
    __nv_bfloat16* Cs = (__nv_bfloat16*)sm;  // stride 136 elems (272B)
#pragma unroll
    for (int i = 0; i < 2; ++i) {
        const int r = m0b + i * 16 + (lane >> 2);
#pragma unroll
        for (int j = 0; j < 8; ++j) {
            const int c = n0b + j * 8 + (lane & 3) * 2;
            *(uint32_t*)(Cs + (size_t)r * 136 + c)       = pack_bf2(acc[i][j][0], acc[i][j][1]);
            *(uint32_t*)(Cs + (size_t)(r + 8) * 136 + c) = pack_bf2(acc[i][j][2], acc[i][j][3]);
        }
    }
    __syncthreads();
    __nv_bfloat16* S = g_Sh + (size_t)b * SEQ * SEQ;
#pragma unroll
    for (int j = 0; j < 8; ++j) {
        int idx = tid + 256 * j;
        int r = idx >> 4, s = idx & 15;
        *(uint4*)(S + (size_t)(row0 + r) * SEQ + col0 + s * 8) =
            *(const uint4*)(Cs + (size_t)r * 136 + s * 8);
    }
}

// ======================= K4: fused stats + exp + Z per row =======================
__global__ __launch_bounds__(256) void expz_kernel()
{
    const int row = blockIdx.x, tid = threadIdx.x;
    const int wid = tid >> 5, lane = tid & 31;
    uint4* srow = (uint4*)(g_Sh + (size_t)row * SEQ);
    uint4 d0 = srow[tid], d1 = srow[tid + 256];
    float f[16];
    {
        const uint32_t* u0 = (const uint32_t*)&d0;
        const uint32_t* u1 = (const uint32_t*)&d1;
#pragma unroll
        for (int i = 0; i < 4; ++i) {
            float2 a = __bfloat1622float2(*(__nv_bfloat162*)&u0[i]);
            f[2 * i] = a.x; f[2 * i + 1] = a.y;
            float2 c = __bfloat1622float2(*(__nv_bfloat162*)&u1[i]);
            f[8 + 2 * i] = c.x; f[9 + 2 * i] = c.y;
        }
    }
    float sum = 0.f, ss = 0.f;
#pragma unroll
    for (int i = 0; i < 16; ++i) { sum += f[i]; ss = fmaf(f[i], f[i], ss); }
#pragma unroll
    for (int o = 16; o > 0; o >>= 1) {
        sum += __shfl_xor_sync(~0u, sum, o);
        ss  += __shfl_xor_sync(~0u, ss, o);
    }
    __shared__ float sA[8], sB[8], sbc[2];
    if (lane == 0) { sA[wid] = sum; sB[wid] = ss; }
    __syncthreads();
    if (tid == 0) {
        float s = 0.f, q = 0.f;
#pragma unroll
        for (int i = 0; i < 8; ++i) { s += sA[i]; q += sB[i]; }
        float mu = s * (1.f / SEQ);
        float var = q * (1.f / SEQ) - mu * mu;
        float c = rsqrtf(var + 1e-5f) * 0.0625f;
        sbc[0] = c; sbc[1] = mu * c;
    }
    __syncthreads();
    const float c = sbc[0], mc = sbc[1];
    float z = 0.f;
#pragma unroll
    for (int i = 0; i < 16; ++i) {
        float e = __expf(fmaf(f[i], c, -mc));
        f[i] = e; z += e;
    }
#pragma unroll
    for (int o = 16; o > 0; o >>= 1) z += __shfl_xor_sync(~0u, z, o);
    if (lane == 0) sA[wid] = z;
    uint4 o0, o1;
    {
        uint32_t* u0 = (uint32_t*)&o0;
        uint32_t* u1 = (uint32_t*)&o1;
#pragma unroll
        for (int i = 0; i < 4; ++i) {
            u0[i] = pack_bf2(f[2 * i], f[2 * i + 1]);
            u1[i] = pack_bf2(f[8 + 2 * i], f[9 + 2 * i]);
        }
    }
    srow[tid] = o0; srow[tid + 256] = o1;
    __syncthreads();
    if (tid == 0) {
        float zt = 0.f;
#pragma unroll
        for (int i = 0; i < 8; ++i) zt += sA[i];
        g_invZ[row] = 1.f / zt;
    }
}

// ======================= K5: O = (P V) * invZ (bf16 HMMA, cp.async pipeline) =======================
__global__ __launch_bounds__(256) void pv_mma_kernel()
{
    extern __shared__ __align__(16) char sm[];
    const uint32_t base = smem_u32(sm);
    const int tid = threadIdx.x, lane = tid & 31, wid = tid >> 5;
    const int b = blockIdx.z, row0 = blockIdx.y * 128, col0 = blockIdx.x * 128;
    const int m0b = (wid & 3) * 32, n0b = (wid >> 2) * 64;

    const __nv_bfloat16* P  = g_Sh + (size_t)b * SEQ * SEQ + (size_t)row0 * SEQ;
    const __nv_bfloat16* Vt = g_vt + ((size_t)b * CH + col0) * SEQ;

    float acc[2][8][4];
#pragma unroll
    for (int i = 0; i < 2; ++i)
#pragma unroll
        for (int j = 0; j < 8; ++j)
#pragma unroll
            for (int t = 0; t < 4; ++t) acc[i][j][t] = 0.f;

    auto issue = [&](int i) {
        const int k0 = i * 64;
        const uint32_t so = (uint32_t)(i & 1) * STG;
#pragma unroll
        for (int j = 0; j < 4; ++j) {
            int idx = tid + 256 * j;
            int r = idx >> 3, s = idx & 7;
            CP_ASYNC16(base + so + (uint32_t)r * LD2 + s * 16,
                       P + (size_t)r * SEQ + k0 + s * 8);
            CP_ASYNC16(base + 2 * STG + so + (uint32_t)r * LD2 + s * 16,
                       Vt + (size_t)r * SEQ + k0 + s * 8);
        }
    };

    issue(0); CP_COMMIT();
    for (int i = 0; i < 64; ++i) {
        if (i + 1 < 64) { issue(i + 1); CP_COMMIT(); CP_WAIT(1); }
        else            { CP_WAIT(0); }
        __syncthreads();
        const uint32_t so = (uint32_t)(i & 1) * STG;
#pragma unroll
        for (int ks = 0; ks < 4; ++ks)
            mma_step<LD2>(base + so, base + 2 * STG + so, ks * 32, m0b, n0b, lane, acc);
        __syncthreads();
    }

    // epilogue: * invZ, fp32 store
#pragma unroll
    for (int i = 0; i < 2; ++i) {
        const int rl = m0b + i * 16 + (lane >> 2);
        const float izA = g_invZ[b * SEQ + row0 + rl];
        const float izB = g_invZ[b * SEQ + row0 + rl + 8];
#pragma unroll
        for (int j = 0; j < 8; ++j) {
            const int c = col0 + n0b + j * 8 + (lane & 3) * 2;
            float2 oA = make_float2(acc[i][j][0] * izA, acc[i][j][1] * izA);
            float2 oB = make_float2(acc[i][j][2] * izB, acc[i][j][3] * izB);
            *(float2*)(g_o + (size_t)(b * SEQ + row0 + rl) * CH + c)     = oA;
            *(float2*)(g_o + (size_t)(b * SEQ + row0 + rl + 8) * CH + c) = oB;
        }
    }
}

// ======================= K6: out = (query + O) @ Wm^T + bm (fp32) =======================
__global__ __launch_bounds__(256) void final_kernel(
    const float* __restrict__ query, const float* __restrict__ Wm,
    const float* __restrict__ bm, float* __restrict__ out)
{
    __shared__ float As[8][128];
    __shared__ float Bs[8][128];
    const int row0 = blockIdx.y * 128, col0 = blockIdx.x * 128;
    const int tid = threadIdx.x;
    const int lr = tid >> 1, lk = (tid & 1) << 2;
    const int tx = tid & 15, ty = tid >> 4;

    float acc[8][8];
#pragma unroll
    for (int i = 0; i < 8; ++i)
#pragma unroll
        for (int j = 0; j < 8; ++j) acc[i][j] = 0.f;

    const float* Ap  = query + (size_t)(row0 + lr) * CH + lk;
    const float* A2p = g_o   + (size_t)(row0 + lr) * CH + lk;
    const float* Bp  = Wm    + (size_t)(col0 + lr) * CH + lk;

    for (int k0 = 0; k0 < CH; k0 += 8) {
        float4 av = *(const float4*)(Ap + k0);
        float4 a2 = *(const float4*)(A2p + k0);
        av.x += a2.x; av.y += a2.y; av.z += a2.z; av.w += a2.w;
        float4 bv = *(const float4*)(Bp + k0);
        __syncthreads();
        As[lk + 0][lr] = av.x; As[lk + 1][lr] = av.y;
        As[lk + 2][lr] = av.z; As[lk + 3][lr] = av.w;
        Bs[lk + 0][lr] = bv.x; Bs[lk + 1][lr] = bv.y;
        Bs[lk + 2][lr] = bv.z; Bs[lk + 3][lr] = bv.w;
        __syncthreads();
#pragma unroll
        for (int kk = 0; kk < 8; ++kk) {
            float a[8], bb[8];
            *(float4*)&a[0]  = *(const float4*)&As[kk][ty * 8];
            *(float4*)&a[4]  = *(const float4*)&As[kk][ty * 8 + 4];
            *(float4*)&bb[0] = *(const float4*)&Bs[kk][tx * 8];
            *(float4*)&bb[4] = *(const float4*)&Bs[kk][tx * 8 + 4];
#pragma unroll
            for (int i = 0; i < 8; ++i)
#pragma unroll
                for (int j = 0; j < 8; ++j)
                    acc[i][j] = fmaf(a[i], bb[j], acc[i][j]);
        }
    }
#pragma unroll
    for (int i = 0; i < 8; ++i) {
        const int r = row0 + ty * 8 + i;
#pragma unroll
        for (int j = 0; j < 8; j += 4) {
            const int cidx = col0 + tx * 8 + j;
            float4 o = make_float4(acc[i][j] + bm[cidx], acc[i][j + 1] + bm[cidx + 1],
                                   acc[i][j + 2] + bm[cidx + 2], acc[i][j + 3] + bm[cidx + 3]);
            *(float4*)(out + (size_t)r * CH + cidx) = o;
        }
    }
}

extern "C" void kernel_launch(void* const* d_in, const int* in_sizes, int n_in,
                              void* d_out, int out_size)
{
    const float* query = (const float*)d_in[0];
    const float* key   = (const float*)d_in[1];
    const float* value = (const float*)d_in[2];
    const float* Wq    = (const float*)d_in[3];
    const float* bq    = (const float*)d_in[4];
    const float* Wk    = (const float*)d_in[5];
    const float* bk    = (const float*)d_in[6];
    const float* Wv    = (const float*)d_in[7];
    const float* bv    = (const float*)d_in[8];
    const float* Wm    = (const float*)d_in[9];
    const float* bm    = (const float*)d_in[10];
    float* out = (float*)d_out;

    cudaFuncSetAttribute(proj_mma_kernel, cudaFuncAttributeMaxDynamicSharedMemorySize, DS1);
    cudaFuncSetAttribute(qk_mma_kernel,   cudaFuncAttributeMaxDynamicSharedMemorySize, DS1);
    cudaFuncSetAttribute(pv_mma_kernel,   cudaFuncAttributeMaxDynamicSharedMemorySize, DS2);

    proj_mma_kernel<<<dim3(2, 128, 3), 256, DS1>>>(query, key, value, Wq, bq, Wk, bk, Wv, bv);
    vt_kernel<<<dim3(64, 4, 4), 256>>>();
    qk_mma_kernel<<<dim3(32, 32, 4), 256, DS1>>>();
    expz_kernel<<<ROWS, 256>>>();
    pv_mma_kernel<<<dim3(2, 32, 4), 256, DS2>>>();
    final_kernel<<<dim3(2, 128), 256>>>(query, Wm, bm, out);
}

// round 4
// speedup vs baseline: 5.9689x; 1.1958x over previous
#include <cuda_runtime.h>
#include <cuda_bf16.h>
#include <math.h>
#include <cstdint>

constexpr int BATCH = 4;
constexpr int SEQ   = 4096;
constexpr int CH    = 256;
constexpr int ROWS  = BATCH * SEQ; // 16384

// ---- device scratch ----
__device__ __nv_bfloat16 g_qh[(size_t)ROWS * CH];
__device__ __nv_bfloat16 g_kh[(size_t)ROWS * CH];
__device__ __nv_bfloat16 g_vh[(size_t)ROWS * CH];
__device__ __nv_bfloat16 g_vt[(size_t)BATCH * CH * SEQ];   // V^T per batch: [c][m]
__device__ float         g_o [(size_t)ROWS * CH];
__device__ __nv_bfloat16 g_Sh[(size_t)BATCH * SEQ * SEQ];  // logits -> probs in place (bf16)
__device__ float         g_invZ[ROWS];

// ======================= helpers =======================
__device__ __forceinline__ uint32_t smem_u32(const void* p) {
    uint32_t a;
    asm("{ .reg .u64 t; cvta.to.shared.u64 t, %1; cvt.u32.u64 %0, t; }" : "=r"(a) : "l"(p));
    return a;
}
__device__ __forceinline__ uint32_t pack_bf2(float a, float b) {
    __nv_bfloat162 h = __floats2bfloat162_rn(a, b);
    return *(uint32_t*)&h;
}
__device__ __forceinline__ void ldm_x4(uint32_t (&r)[4], uint32_t addr) {
    asm volatile("ldmatrix.sync.aligned.m8n8.x4.shared.b16 {%0,%1,%2,%3}, [%4];"
        : "=r"(r[0]), "=r"(r[1]), "=r"(r[2]), "=r"(r[3]) : "r"(addr));
}
__device__ __forceinline__ void mma_bf16(float (&d)[4], const uint32_t (&a)[4],
                                         uint32_t b0, uint32_t b1) {
    asm volatile("mma.sync.aligned.m16n8k16.row.col.f32.bf16.bf16.f32 "
        "{%0,%1,%2,%3}, {%4,%5,%6,%7}, {%8,%9}, {%0,%1,%2,%3};"
        : "+f"(d[0]), "+f"(d[1]), "+f"(d[2]), "+f"(d[3])
        : "r"(a[0]), "r"(a[1]), "r"(a[2]), "r"(a[3]), "r"(b0), "r"(b1));
}

#define CP_ASYNC16(dst, src) asm volatile("cp.async.cg.shared.global [%0], [%1], 16;" :: "r"(dst), "l"(src) : "memory")
#define CP_COMMIT()          asm volatile("cp.async.commit_group;" ::: "memory")
#define CP_WAIT(n)           asm volatile("cp.async.wait_group %0;" :: "n"(n) : "memory")

// One k16 MMA step for a 32x64 warp tile from padded smem.
// LDB = smem row stride in BYTES. sa/sb point at tile base (byte smem addrs).
template <int LDB>
__device__ __forceinline__ void mma_step(uint32_t sa, uint32_t sb, int kb,
                                         int m0b, int n0b, int lane,
                                         float (&acc)[2][8][4])
{
    uint32_t a[2][4];
#pragma unroll
    for (int i = 0; i < 2; ++i)
        ldm_x4(a[i], sa + (uint32_t)(m0b + i * 16 + (lane & 15)) * LDB + kb + ((lane >> 4) << 4));
    uint32_t bb[4][4];
#pragma unroll
    for (int p = 0; p < 4; ++p)
        ldm_x4(bb[p], sb + (uint32_t)(n0b + p * 16 + ((lane >> 4) << 3) + (lane & 7)) * LDB
                      + kb + (((lane >> 3) & 1) << 4));
#pragma unroll
    for (int i = 0; i < 2; ++i)
#pragma unroll
        for (int j = 0; j < 8; ++j)
            mma_bf16(acc[i][j], a[i], bb[j >> 1][(j & 1) * 2], bb[j >> 1][(j & 1) * 2 + 1]);
}

// strides
constexpr int LD1 = 528;            // 256 bf16 + 8 pad = 264 elems -> 528 bytes
constexpr int DS1 = 2 * 128 * LD1;  // 135168 (A + B tiles, K=256 one-shot)
constexpr int LD2 = 144;            // 64 bf16 + 8 pad = 72 elems -> 144 bytes
constexpr int STG = 128 * LD2;      // 18432 per stage/tile
constexpr int DS2 = 4 * STG;        // 73728

// ======================= K1: projections (bf16 HMMA, K=256 one-shot) =======================
__global__ __launch_bounds__(256) void proj_mma_kernel(
    const float* __restrict__ q, const float* __restrict__ k, const float* __restrict__ v,
    const float* __restrict__ Wq, const float* __restrict__ bq,
    const float* __restrict__ Wk, const float* __restrict__ bk,
    const float* __restrict__ Wv, const float* __restrict__ bv)
{
    extern __shared__ __align__(16) char sm[];
    const uint32_t base = smem_u32(sm);
    const int tid = threadIdx.x, lane = tid & 31, wid = tid >> 5;
    const int row0 = blockIdx.y * 128, col0 = blockIdx.x * 128;
    const int m0b = (wid & 3) * 32, n0b = (wid >> 2) * 64;

    const float *X, *W, *bias; __nv_bfloat16* Y;
    if (blockIdx.z == 0)      { X = q; W = Wq; bias = bq; Y = g_qh; }
    else if (blockIdx.z == 1) { X = k; W = Wk; bias = bk; Y = g_kh; }
    else                      { X = v; W = Wv; bias = bv; Y = g_vh; }

#pragma unroll
    for (int j = 0; j < 16; ++j) {
        int idx = tid + 256 * j;
        int r = idx >> 5, s = idx & 31;
        const float* xa = X + (size_t)(row0 + r) * CH + s * 8;
        float4 x0 = *(const float4*)xa, x1 = *(const float4*)(xa + 4);
        uint4 av = make_uint4(pack_bf2(x0.x, x0.y), pack_bf2(x0.z, x0.w),
                              pack_bf2(x1.x, x1.y), pack_bf2(x1.z, x1.w));
        *(uint4*)(sm + (size_t)r * LD1 + s * 16) = av;
        const float* wa = W + (size_t)(col0 + r) * CH + s * 8;
        float4 w0 = *(const float4*)wa, w1 = *(const float4*)(wa + 4);
        uint4 bv2 = make_uint4(pack_bf2(w0.x, w0.y), pack_bf2(w0.z, w0.w),
                               pack_bf2(w1.x, w1.y), pack_bf2(w1.z, w1.w));
        *(uint4*)(sm + 128 * LD1 + (size_t)r * LD1 + s * 16) = bv2;
    }
    __syncthreads();

    float acc[2][8][4];
#pragma unroll
    for (int i = 0; i < 2; ++i)
#pragma unroll
        for (int j = 0; j < 8; ++j)
#pragma unroll
            for (int t = 0; t < 4; ++t) acc[i][j][t] = 0.f;

#pragma unroll
    for (int ks = 0; ks < 16; ++ks)
        mma_step<LD1>(base, base + 128 * LD1, ks * 32, m0b, n0b, lane, acc);

#pragma unroll
    for (int i = 0; i < 2; ++i) {
        const int r = row0 + m0b + i * 16 + (lane >> 2);
#pragma unroll
        for (int j = 0; j < 8; ++j) {
            const int c = col0 + n0b + j * 8 + (lane & 3) * 2;
            float2 bv2 = *(const float2*)(bias + c);
            *(uint32_t*)(Y + (size_t)r * CH + c) =
                pack_bf2(acc[i][j][0] + bv2.x, acc[i][j][1] + bv2.y);
            *(uint32_t*)(Y + (size_t)(r + 8) * CH + c) =
                pack_bf2(acc[i][j][2] + bv2.x, acc[i][j][3] + bv2.y);
        }
    }
}

// ======================= K2: V transpose (bf16) =======================
__global__ __launch_bounds__(256) void vt_kernel()
{
    __shared__ __nv_bfloat16 t[64][72];
    const int b = blockIdx.z, m0 = blockIdx.x * 64, c0 = blockIdx.y * 64;
    const __nv_bfloat16* src = g_vh + ((size_t)b * SEQ + m0) * CH + c0;
#pragma unroll
    for (int j = 0; j < 2; ++j) {
        int idx = threadIdx.x + 256 * j;
        int r = idx >> 3, cu = idx & 7;
        *(uint4*)&t[r][cu * 8] = *(const uint4*)(src + (size_t)r * CH + cu * 8);
    }
    __syncthreads();
    __nv_bfloat16* dst = g_vt + ((size_t)b * CH + c0) * SEQ + m0;
#pragma unroll
    for (int j = 0; j < 2; ++j) {
        int idx = threadIdx.x + 256 * j;
        int c = idx >> 3, mu = idx & 7;
        __nv_bfloat16 tmp[8];
#pragma unroll
        for (int i = 0; i < 8; ++i) tmp[i] = t[mu * 8 + i][c];
        *(uint4*)(dst + (size_t)c * SEQ + mu * 8) = *(uint4*)tmp;
    }
}

// ======================= K3: S = q k^T (bf16 HMMA, cp.async pipelined) =======================
__global__ __launch_bounds__(256, 2) void qk_mma_kernel()
{
    extern __shared__ __align__(16) char sm[];
    const uint32_t base = smem_u32(sm);
    const int tid = threadIdx.x, lane = tid & 31, wid = tid >> 5;
    const int b = blockIdx.z, row0 = blockIdx.y * 128, col0 = blockIdx.x * 128;
    const int m0b = (wid & 3) * 32, n0b = (wid >> 2) * 64;

    const __nv_bfloat16* A = g_qh + ((size_t)b * SEQ + row0) * CH;
    const __nv_bfloat16* B = g_kh + ((size_t)b * SEQ + col0) * CH;

    float acc[2][8][4];
#pragma unroll
    for (int i = 0; i < 2; ++i)
#pragma unroll
        for (int j = 0; j < 8; ++j)
#pragma unroll
            for (int t = 0; t < 4; ++t) acc[i][j][t] = 0.f;

    auto issue = [&](int i) {
        const int k0 = i * 64;
        const uint32_t so = (uint32_t)(i & 1) * STG;
#pragma unroll
        for (int j = 0; j < 4; ++j) {
            int idx = tid + 256 * j;
            int r = idx >> 3, s = idx & 7;
            CP_ASYNC16(base + so + (uint32_t)r * LD2 + s * 16,
                       A + (size_t)r * CH + k0 + s * 8);
            CP_ASYNC16(base + 2 * STG + so + (uint32_t)r * LD2 + s * 16,
                       B + (size_t)r * CH + k0 + s * 8);
        }
    };

    issue(0); CP_COMMIT();
    for (int i = 0; i < 4; ++i) {
        if (i + 1 < 4) { issue(i + 1); CP_COMMIT(); CP_WAIT(1); }
        else           { CP_WAIT(0); }
        __syncthreads();
        const uint32_t so = (uint32_t)(i & 1) * STG;
#pragma unroll
        for (int ks = 0; ks < 4; ++ks)
            mma_step<LD2>(base + so, base + 2 * STG + so, ks * 32, m0b, n0b, lane, acc);
        __syncthreads();
    }

    // stage C (bf16) through smem for coalesced global writes
    __nv_bfloat16* Cs = (__nv_bfloat16*)sm;  // stride 136 elems (272B)
#pragma unroll
    for (int i = 0; i < 2; ++i) {
        const int r = m0b + i * 16 + (lane >> 2);
#pragma unroll
        for (int j = 0; j < 8; ++j) {
            const int c = n0b + j * 8 + (lane & 3) * 2;
            *(uint32_t*)(Cs + (size_t)r * 136 + c)       = pack_bf2(acc[i][j][0], acc[i][j][1]);
            *(uint32_t*)(Cs + (size_t)(r + 8) * 136 + c) = pack_bf2(acc[i][j][2], acc[i][j][3]);
        }
    }
    __syncthreads();
    __nv_bfloat16* S = g_Sh + (size_t)b * SEQ * SEQ;
#pragma unroll
    for (int j = 0; j < 8; ++j) {
        int idx = tid + 256 * j;
        int r = idx >> 4, s = idx & 15;
        *(uint4*)(S + (size_t)(row0 + r) * SEQ + col0 + s * 8) =
            *(const uint4*)(Cs + (size_t)r * 136 + s * 8);
    }
}

// ======================= K4: fused stats + exp + Z per row (512 thr) =======================
__global__ __launch_bounds__(512) void expz_kernel()
{
    const int row = blockIdx.x, tid = threadIdx.x;
    const int wid = tid >> 5, lane = tid & 31;
    uint4* srow = (uint4*)(g_Sh + (size_t)row * SEQ);   // 512 uint4 per row
    uint4 d = srow[tid];
    float f[8];
    {
        const uint32_t* u = (const uint32_t*)&d;
#pragma unroll
        for (int i = 0; i < 4; ++i) {
            float2 a = __bfloat1622float2(*(__nv_bfloat162*)&u[i]);
            f[2 * i] = a.x; f[2 * i + 1] = a.y;
        }
    }
    float sum = 0.f, ss = 0.f;
#pragma unroll
    for (int i = 0; i < 8; ++i) { sum += f[i]; ss = fmaf(f[i], f[i], ss); }
#pragma unroll
    for (int o = 16; o > 0; o >>= 1) {
        sum += __shfl_xor_sync(~0u, sum, o);
        ss  += __shfl_xor_sync(~0u, ss, o);
    }
    __shared__ float sA[16], sB[16], sbc[2];
    if (lane == 0) { sA[wid] = sum; sB[wid] = ss; }
    __syncthreads();
    if (tid == 0) {
        float s = 0.f, q = 0.f;
#pragma unroll
        for (int i = 0; i < 16; ++i) { s += sA[i]; q += sB[i]; }
        float mu = s * (1.f / SEQ);
        float var = q * (1.f / SEQ) - mu * mu;
        float c = rsqrtf(var + 1e-5f) * 0.0625f;
        sbc[0] = c; sbc[1] = mu * c;
    }
    __syncthreads();
    const float c = sbc[0], mc = sbc[1];
    float z = 0.f;
#pragma unroll
    for (int i = 0; i < 8; ++i) {
        float e = __expf(fmaf(f[i], c, -mc));
        f[i] = e; z += e;
    }
#pragma unroll
    for (int o = 16; o > 0; o >>= 1) z += __shfl_xor_sync(~0u, z, o);
    if (lane == 0) sA[wid] = z;
    uint4 o0;
    {
        uint32_t* u = (uint32_t*)&o0;
#pragma unroll
        for (int i = 0; i < 4; ++i) u[i] = pack_bf2(f[2 * i], f[2 * i + 1]);
    }
    srow[tid] = o0;
    __syncthreads();
    if (tid == 0) {
        float zt = 0.f;
#pragma unroll
        for (int i = 0; i < 16; ++i) zt += sA[i];
        g_invZ[row] = 1.f / zt;
    }
}

// ======================= K5: O = (P V) * invZ (bf16 HMMA, cp.async pipeline) =======================
__global__ __launch_bounds__(256, 2) void pv_mma_kernel()
{
    extern __shared__ __align__(16) char sm[];
    const uint32_t base = smem_u32(sm);
    const int tid = threadIdx.x, lane = tid & 31, wid = tid >> 5;
    const int b = blockIdx.z, row0 = blockIdx.y * 128, col0 = blockIdx.x * 128;
    const int m0b = (wid & 3) * 32, n0b = (wid >> 2) * 64;

    const __nv_bfloat16* P  = g_Sh + (size_t)b * SEQ * SEQ + (size_t)row0 * SEQ;
    const __nv_bfloat16* Vt = g_vt + ((size_t)b * CH + col0) * SEQ;

    float acc[2][8][4];
#pragma unroll
    for (int i = 0; i < 2; ++i)
#pragma unroll
        for (int j = 0; j < 8; ++j)
#pragma unroll
            for (int t = 0; t < 4; ++t) acc[i][j][t] = 0.f;

    auto issue = [&](int i) {
        const int k0 = i * 64;
        const uint32_t so = (uint32_t)(i & 1) * STG;
#pragma unroll
        for (int j = 0; j < 4; ++j) {
            int idx = tid + 256 * j;
            int r = idx >> 3, s = idx & 7;
            CP_ASYNC16(base + so + (uint32_t)r * LD2 + s * 16,
                       P + (size_t)r * SEQ + k0 + s * 8);
            CP_ASYNC16(base + 2 * STG + so + (uint32_t)r * LD2 + s * 16,
                       Vt + (size_t)r * SEQ + k0 + s * 8);
        }
    };

    issue(0); CP_COMMIT();
    for (int i = 0; i < 64; ++i) {
        if (i + 1 < 64) { issue(i + 1); CP_COMMIT(); CP_WAIT(1); }
        else            { CP_WAIT(0); }
        __syncthreads();
        const uint32_t so = (uint32_t)(i & 1) * STG;
#pragma unroll
        for (int ks = 0; ks < 4; ++ks)
            mma_step<LD2>(base + so, base + 2 * STG + so, ks * 32, m0b, n0b, lane, acc);
        __syncthreads();
    }

#pragma unroll
    for (int i = 0; i < 2; ++i) {
        const int rl = m0b + i * 16 + (lane >> 2);
        const float izA = g_invZ[b * SEQ + row0 + rl];
        const float izB = g_invZ[b * SEQ + row0 + rl + 8];
#pragma unroll
        for (int j = 0; j < 8; ++j) {
            const int c = col0 + n0b + j * 8 + (lane & 3) * 2;
            float2 oA = make_float2(acc[i][j][0] * izA, acc[i][j][1] * izA);
            float2 oB = make_float2(acc[i][j][2] * izB, acc[i][j][3] * izB);
            *(float2*)(g_o + (size_t)(b * SEQ + row0 + rl) * CH + c)     = oA;
            *(float2*)(g_o + (size_t)(b * SEQ + row0 + rl + 8) * CH + c) = oB;
        }
    }
}

// ======================= K6: out = (query + O) @ Wm^T + bm (bf16x3 HMMA) =======================
// A = query + O split into hi+lo bf16; B = Wm split into hi+lo bf16.
// acc += ahi*bhi + ahi*blo + alo*bhi  (drops lo*lo ~2^-17 relative).
__global__ __launch_bounds__(256) void final_mma_kernel(
    const float* __restrict__ query, const float* __restrict__ Wm,
    const float* __restrict__ bm, float* __restrict__ out)
{
    extern __shared__ __align__(16) char sm[];
    const uint32_t base = smem_u32(sm);
    const uint32_t sAhi = base, sAlo = base + STG, sBhi = base + 2 * STG, sBlo = base + 3 * STG;
    const int tid = threadIdx.x, lane = tid & 31, wid = tid >> 5;
    const int row0 = blockIdx.y * 128, col0 = blockIdx.x * 128;
    const int m0b = (wid & 3) * 32, n0b = (wid >> 2) * 64;

    float acc[2][8][4];
#pragma unroll
    for (int i = 0; i < 2; ++i)
#pragma unroll
        for (int j = 0; j < 8; ++j)
#pragma unroll
            for (int t = 0; t < 4; ++t) acc[i][j][t] = 0.f;

    for (int ch = 0; ch < 4; ++ch) {
        const int k0 = ch * 64;
        __syncthreads();
        // load + split: 128 rows x 64 cols, 8 elems per unit, 1024 units
#pragma unroll
        for (int j = 0; j < 4; ++j) {
            int idx = tid + 256 * j;
            int r = idx >> 3, s = idx & 7;
            const float* qa = query + (size_t)(row0 + r) * CH + k0 + s * 8;
            const float* oa = g_o   + (size_t)(row0 + r) * CH + k0 + s * 8;
            float av[8];
            *(float4*)&av[0] = *(const float4*)qa;
            *(float4*)&av[4] = *(const float4*)(qa + 4);
            float4 o0 = *(const float4*)oa, o1 = *(const float4*)(oa + 4);
            av[0] += o0.x; av[1] += o0.y; av[2] += o0.z; av[3] += o0.w;
            av[4] += o1.x; av[5] += o1.y; av[6] += o1.z; av[7] += o1.w;
            uint4 hi, lo;
            uint32_t* hp = (uint32_t*)&hi; uint32_t* lp = (uint32_t*)&lo;
#pragma unroll
            for (int t = 0; t < 4; ++t) {
                float a0 = av[2 * t], a1 = av[2 * t + 1];
                __nv_bfloat16 h0 = __float2bfloat16_rn(a0), h1 = __float2bfloat16_rn(a1);
                float l0 = a0 - __bfloat162float(h0), l1 = a1 - __bfloat162float(h1);
                hp[t] = ((uint32_t)*(uint16_t*)&h1 << 16) | *(uint16_t*)&h0;
                lp[t] = pack_bf2(l0, l1);
            }
            const uint32_t doff = (uint32_t)r * LD2 + s * 16;
            *(uint4*)(sm + doff)        = hi;
            *(uint4*)(sm + STG + doff)  = lo;

            const float* wa = Wm + (size_t)(col0 + r) * CH + k0 + s * 8;
            float wv[8];
            *(float4*)&wv[0] = *(const float4*)wa;
            *(float4*)&wv[4] = *(const float4*)(wa + 4);
#pragma unroll
            for (int t = 0; t < 4; ++t) {
                float a0 = wv[2 * t], a1 = wv[2 * t + 1];
                __nv_bfloat16 h0 = __float2bfloat16_rn(a0), h1 = __float2bfloat16_rn(a1);
                float l0 = a0 - __bfloat162float(h0), l1 = a1 - __bfloat162float(h1);
                hp[t] = ((uint32_t)*(uint16_t*)&h1 << 16) | *(uint16_t*)&h0;
                lp[t] = pack_bf2(l0, l1);
            }
            *(uint4*)(sm + 2 * STG + doff) = hi;
            *(uint4*)(sm + 3 * STG + doff) = lo;
        }
        __syncthreads();

#pragma unroll
        for (int ks = 0; ks < 4; ++ks) {
            const int kb = ks * 32;
            uint32_t ah[2][4], al[2][4];
#pragma unroll
            for (int i = 0; i < 2; ++i) {
                const uint32_t ao = (uint32_t)(m0b + i * 16 + (lane & 15)) * LD2 + kb + ((lane >> 4) << 4);
                ldm_x4(ah[i], sAhi + ao);
                ldm_x4(al[i], sAlo + ao);
            }
            uint32_t bh[4][4], bl[4][4];
#pragma unroll
            for (int p = 0; p < 4; ++p) {
                const uint32_t bo = (uint32_t)(n0b + p * 16 + ((lane >> 4) << 3) + (lane & 7)) * LD2
                                    + kb + (((lane >> 3) & 1) << 4);
                ldm_x4(bh[p], sBhi + bo);
                ldm_x4(bl[p], sBlo + bo);
            }
#pragma unroll
            for (int i = 0; i < 2; ++i)
#pragma unroll
                for (int j = 0; j < 8; ++j) {
                    uint32_t bh0 = bh[j >> 1][(j & 1) * 2], bh1 = bh[j >> 1][(j & 1) * 2 + 1];
                    uint32_t bl0 = bl[j >> 1][(j & 1) * 2], bl1 = bl[j >> 1][(j & 1) * 2 + 1];
                    mma_bf16(acc[i][j], ah[i], bh0, bh1);
                    mma_bf16(acc[i][j], ah[i], bl0, bl1);
                    mma_bf16(acc[i][j], al[i], bh0, bh1);
                }
        }
    }

#pragma unroll
    for (int i = 0; i < 2; ++i) {
        const int r = row0 + m0b + i * 16 + (lane >> 2);
#pragma unroll
        for (int j = 0; j < 8; ++j) {
            const int c = col0 + n0b + j * 8 + (lane & 3) * 2;
            float2 bv2 = *(const float2*)(bm + c);
            *(float2*)(out + (size_t)r * CH + c) =
                make_float2(acc[i][j][0] + bv2.x, acc[i][j][1] + bv2.y);
            *(float2*)(out + (size_t)(r + 8) * CH + c) =
                make_float2(acc[i][j][2] + bv2.x, acc[i][j][3] + bv2.y);
        }
    }
}

extern "C" void kernel_launch(void* const* d_in, const int* in_sizes, int n_in,
                              void* d_out, int out_size)
{
    const float* query = (const float*)d_in[0];
    const float* key   = (const float*)d_in[1];
    const float* value = (const float*)d_in[2];
    const float* Wq    = (const float*)d_in[3];
    const float* bq    = (const float*)d_in[4];
    const float* Wk    = (const float*)d_in[5];
    const float* bk    = (const float*)d_in[6];
    const float* Wv    = (const float*)d_in[7];
    const float* bv    = (const float*)d_in[8];
    const float* Wm    = (const float*)d_in[9];
    const float* bm    = (const float*)d_in[10];
    float* out = (float*)d_out;

    cudaFuncSetAttribute(proj_mma_kernel,  cudaFuncAttributeMaxDynamicSharedMemorySize, DS1);
    cudaFuncSetAttribute(qk_mma_kernel,    cudaFuncAttributeMaxDynamicSharedMemorySize, DS2);
    cudaFuncSetAttribute(pv_mma_kernel,    cudaFuncAttributeMaxDynamicSharedMemorySize, DS2);
    cudaFuncSetAttribute(final_mma_kernel, cudaFuncAttributeMaxDynamicSharedMemorySize, DS2);

    proj_mma_kernel<<<dim3(2, 128, 3), 256, DS1>>>(query, key, value, Wq, bq, Wk, bk, Wv, bv);
    vt_kernel<<<dim3(64, 4, 4), 256>>>();
    qk_mma_kernel<<<dim3(32, 32, 4), 256, DS2>>>();
    expz_kernel<<<ROWS, 512>>>();
    pv_mma_kernel<<<dim3(2, 32, 4), 256, DS2>>>();
    final_mma_kernel<<<dim3(2, 128), 256, DS2>>>(query, Wm, bm, out);
}

// round 5
// speedup vs baseline: 6.2228x; 1.0425x over previous
#include <cuda_runtime.h>
#include <cuda_bf16.h>
#include <math.h>
#include <cstdint>

constexpr int BATCH = 4;
constexpr int SEQ   = 4096;
constexpr int CH    = 256;
constexpr int ROWS  = BATCH * SEQ; // 16384

// ---- device scratch ----
__device__ __nv_bfloat16 g_qh[(size_t)ROWS * CH];
__device__ __nv_bfloat16 g_kh[(size_t)ROWS * CH];
__device__ __nv_bfloat16 g_vh[(size_t)ROWS * CH];
__device__ __nv_bfloat16 g_vt[(size_t)BATCH * CH * SEQ];   // V^T per batch: [c][m]
__device__ float         g_o [(size_t)ROWS * CH];
__device__ __nv_bfloat16 g_Sh[(size_t)BATCH * SEQ * SEQ];  // logits -> probs in place (bf16)
__device__ float         g_invZ[ROWS];

// ======================= helpers =======================
__device__ __forceinline__ uint32_t smem_u32(const void* p) {
    uint32_t a;
    asm("{ .reg .u64 t; cvta.to.shared.u64 t, %1; cvt.u32.u64 %0, t; }" : "=r"(a) : "l"(p));
    return a;
}
__device__ __forceinline__ uint32_t pack_bf2(float a, float b) {
    __nv_bfloat162 h = __floats2bfloat162_rn(a, b);
    return *(uint32_t*)&h;
}
__device__ __forceinline__ void ldm_x4(uint32_t (&r)[4], uint32_t addr) {
    asm volatile("ldmatrix.sync.aligned.m8n8.x4.shared.b16 {%0,%1,%2,%3}, [%4];"
        : "=r"(r[0]), "=r"(r[1]), "=r"(r[2]), "=r"(r[3]) : "r"(addr));
}
__device__ __forceinline__ void mma_bf16(float (&d)[4], const uint32_t (&a)[4],
                                         uint32_t b0, uint32_t b1) {
    asm volatile("mma.sync.aligned.m16n8k16.row.col.f32.bf16.bf16.f32 "
        "{%0,%1,%2,%3}, {%4,%5,%6,%7}, {%8,%9}, {%0,%1,%2,%3};"
        : "+f"(d[0]), "+f"(d[1]), "+f"(d[2]), "+f"(d[3])
        : "r"(a[0]), "r"(a[1]), "r"(a[2]), "r"(a[3]), "r"(b0), "r"(b1));
}

#define CP_ASYNC16(dst, src) asm volatile("cp.async.cg.shared.global [%0], [%1], 16;" :: "r"(dst), "l"(src) : "memory")
#define CP_COMMIT()          asm volatile("cp.async.commit_group;" ::: "memory")
#define CP_WAIT(n)           asm volatile("cp.async.wait_group %0;" :: "n"(n) : "memory")

// One k16 MMA step for a 32x64 warp tile from padded smem.
template <int LDB>
__device__ __forceinline__ void mma_step(uint32_t sa, uint32_t sb, int kb,
                                         int m0b, int n0b, int lane,
                                         float (&acc)[2][8][4])
{
    uint32_t a[2][4];
#pragma unroll
    for (int i = 0; i < 2; ++i)
        ldm_x4(a[i], sa + (uint32_t)(m0b + i * 16 + (lane & 15)) * LDB + kb + ((lane >> 4) << 4));
    uint32_t bb[4][4];
#pragma unroll
    for (int p = 0; p < 4; ++p)
        ldm_x4(bb[p], sb + (uint32_t)(n0b + p * 16 + ((lane >> 4) << 3) + (lane & 7)) * LDB
                      + kb + (((lane >> 3) & 1) << 4));
#pragma unroll
    for (int i = 0; i < 2; ++i)
#pragma unroll
        for (int j = 0; j < 8; ++j)
            mma_bf16(acc[i][j], a[i], bb[j >> 1][(j & 1) * 2], bb[j >> 1][(j & 1) * 2 + 1]);
}

// strides
constexpr int LD1 = 528;            // 256 bf16 + 8 pad = 264 elems -> 528 bytes
constexpr int DS1 = 2 * 128 * LD1;  // 135168
constexpr int LD2 = 144;            // 64 bf16 + 8 pad = 72 elems -> 144 bytes
constexpr int STG = 128 * LD2;      // 18432 per tile (128 rows x 64 cols bf16)
constexpr int DS3 = 6 * STG;        // 110592: 3 stages x (A,B)

// 3-stage cp.async pipelined NT-fragment GEMM mainloop over K = NCHUNK*64.
// A rows: M dim (128), stride lda elems. B rows: N dim (128), stride ldb elems.
template <int NCHUNK>
__device__ __forceinline__ void gemm_pipe(
    const __nv_bfloat16* __restrict__ A, size_t lda,
    const __nv_bfloat16* __restrict__ B, size_t ldb,
    uint32_t base, char* sm, int tid, int m0b, int n0b, int lane,
    float (&acc)[2][8][4])
{
    auto issue = [&](int i) {
        const int k0 = i * 64;
        const uint32_t so = (uint32_t)(i % 3) * (2 * STG);
#pragma unroll
        for (int j = 0; j < 4; ++j) {
            int idx = tid + 256 * j;
            int r = idx >> 3, s = idx & 7;
            CP_ASYNC16(base + so + (uint32_t)r * LD2 + s * 16,
                       A + (size_t)r * lda + k0 + s * 8);
            CP_ASYNC16(base + so + STG + (uint32_t)r * LD2 + s * 16,
                       B + (size_t)r * ldb + k0 + s * 8);
        }
        CP_COMMIT();
    };

    issue(0);
    if (NCHUNK > 1) issue(1);
    for (int i = 0; i < NCHUNK; ++i) {
        if (i + 1 < NCHUNK) { CP_WAIT(1); } else { CP_WAIT(0); }
        __syncthreads();
        if (i + 2 < NCHUNK) issue(i + 2);
        const uint32_t so = (uint32_t)(i % 3) * (2 * STG);
#pragma unroll
        for (int ks = 0; ks < 4; ++ks)
            mma_step<LD2>(base + so, base + so + STG, ks * 32, m0b, n0b, lane, acc);
    }
}

// ======================= K1: projections (bf16 HMMA, K=256 one-shot) =======================
__global__ __launch_bounds__(256) void proj_mma_kernel(
    const float* __restrict__ q, const float* __restrict__ k, const float* __restrict__ v,
    const float* __restrict__ Wq, const float* __restrict__ bq,
    const float* __restrict__ Wk, const float* __restrict__ bk,
    const float* __restrict__ Wv, const float* __restrict__ bv)
{
    extern __shared__ __align__(16) char sm[];
    const uint32_t base = smem_u32(sm);
    const int tid = threadIdx.x, lane = tid & 31, wid = tid >> 5;
    const int row0 = blockIdx.y * 128, col0 = blockIdx.x * 128;
    const int m0b = (wid & 3) * 32, n0b = (wid >> 2) * 64;

    const float *X, *W, *bias; __nv_bfloat16* Y;
    if (blockIdx.z == 0)      { X = q; W = Wq; bias = bq; Y = g_qh; }
    else if (blockIdx.z == 1) { X = k; W = Wk; bias = bk; Y = g_kh; }
    else                      { X = v; W = Wv; bias = bv; Y = g_vh; }

#pragma unroll
    for (int j = 0; j < 16; ++j) {
        int idx = tid + 256 * j;
        int r = idx >> 5, s = idx & 31;
        const float* xa = X + (size_t)(row0 + r) * CH + s * 8;
        float4 x0 = *(const float4*)xa, x1 = *(const float4*)(xa + 4);
        uint4 av = make_uint4(pack_bf2(x0.x, x0.y), pack_bf2(x0.z, x0.w),
                              pack_bf2(x1.x, x1.y), pack_bf2(x1.z, x1.w));
        *(uint4*)(sm + (size_t)r * LD1 + s * 16) = av;
        const float* wa = W + (size_t)(col0 + r) * CH + s * 8;
        float4 w0 = *(const float4*)wa, w1 = *(const float4*)(wa + 4);
        uint4 bv2 = make_uint4(pack_bf2(w0.x, w0.y), pack_bf2(w0.z, w0.w),
                               pack_bf2(w1.x, w1.y), pack_bf2(w1.z, w1.w));
        *(uint4*)(sm + 128 * LD1 + (size_t)r * LD1 + s * 16) = bv2;
    }
    __syncthreads();

    float acc[2][8][4];
#pragma unroll
    for (int i = 0; i < 2; ++i)
#pragma unroll
        for (int j = 0; j < 8; ++j)
#pragma unroll
            for (int t = 0; t < 4; ++t) acc[i][j][t] = 0.f;

#pragma unroll
    for (int ks = 0; ks < 16; ++ks)
        mma_step<LD1>(base, base + 128 * LD1, ks * 32, m0b, n0b, lane, acc);

#pragma unroll
    for (int i = 0; i < 2; ++i) {
        const int r = row0 + m0b + i * 16 + (lane >> 2);
#pragma unroll
        for (int j = 0; j < 8; ++j) {
            const int c = col0 + n0b + j * 8 + (lane & 3) * 2;
            float2 bv2 = *(const float2*)(bias + c);
            *(uint32_t*)(Y + (size_t)r * CH + c) =
                pack_bf2(acc[i][j][0] + bv2.x, acc[i][j][1] + bv2.y);
            *(uint32_t*)(Y + (size_t)(r + 8) * CH + c) =
                pack_bf2(acc[i][j][2] + bv2.x, acc[i][j][3] + bv2.y);
        }
    }
}

// ======================= K2: V transpose (bf16) =======================
__global__ __launch_bounds__(256) void vt_kernel()
{
    __shared__ __nv_bfloat16 t[64][72];
    const int b = blockIdx.z, m0 = blockIdx.x * 64, c0 = blockIdx.y * 64;
    const __nv_bfloat16* src = g_vh + ((size_t)b * SEQ + m0) * CH + c0;
#pragma unroll
    for (int j = 0; j < 2; ++j) {
        int idx = threadIdx.x + 256 * j;
        int r = idx >> 3, cu = idx & 7;
        *(uint4*)&t[r][cu * 8] = *(const uint4*)(src + (size_t)r * CH + cu * 8);
    }
    __syncthreads();
    __nv_bfloat16* dst = g_vt + ((size_t)b * CH + c0) * SEQ + m0;
#pragma unroll
    for (int j = 0; j < 2; ++j) {
        int idx = threadIdx.x + 256 * j;
        int c = idx >> 3, mu = idx & 7;
        __nv_bfloat16 tmp[8];
#pragma unroll
        for (int i = 0; i < 8; ++i) tmp[i] = t[mu * 8 + i][c];
        *(uint4*)(dst + (size_t)c * SEQ + mu * 8) = *(uint4*)tmp;
    }
}

// ======================= K3: S = q k^T (bf16 HMMA, 3-stage pipeline) =======================
__global__ __launch_bounds__(256, 2) void qk_mma_kernel()
{
    extern __shared__ __align__(16) char sm[];
    const uint32_t base = smem_u32(sm);
    const int tid = threadIdx.x, lane = tid & 31, wid = tid >> 5;
    const int b = blockIdx.z, row0 = blockIdx.y * 128, col0 = blockIdx.x * 128;
    const int m0b = (wid & 3) * 32, n0b = (wid >> 2) * 64;

    float acc[2][8][4];
#pragma unroll
    for (int i = 0; i < 2; ++i)
#pragma unroll
        for (int j = 0; j < 8; ++j)
#pragma unroll
            for (int t = 0; t < 4; ++t) acc[i][j][t] = 0.f;

    gemm_pipe<4>(g_qh + ((size_t)b * SEQ + row0) * CH, CH,
                 g_kh + ((size_t)b * SEQ + col0) * CH, CH,
                 base, sm, tid, m0b, n0b, lane, acc);

    // stage C (bf16) through smem for coalesced global writes
    __syncthreads();
    __nv_bfloat16* Cs = (__nv_bfloat16*)sm;  // stride 136 elems (272B)
#pragma unroll
    for (int i = 0; i < 2; ++i) {
        const int r = m0b + i * 16 + (lane >> 2);
#pragma unroll
        for (int j = 0; j < 8; ++j) {
            const int c = n0b + j * 8 + (lane & 3) * 2;
            *(uint32_t*)(Cs + (size_t)r * 136 + c)       = pack_bf2(acc[i][j][0], acc[i][j][1]);
            *(uint32_t*)(Cs + (size_t)(r + 8) * 136 + c) = pack_bf2(acc[i][j][2], acc[i][j][3]);
        }
    }
    __syncthreads();
    __nv_bfloat16* S = g_Sh + (size_t)b * SEQ * SEQ;
#pragma unroll
    for (int j = 0; j < 8; ++j) {
        int idx = tid + 256 * j;
        int r = idx >> 4, s = idx & 15;
        *(uint4*)(S + (size_t)(row0 + r) * SEQ + col0 + s * 8) =
            *(const uint4*)(Cs + (size_t)r * 136 + s * 8);
    }
}

// ======================= K4: fused stats + exp + Z per row (256 thr, 2x uint4) ============
__global__ __launch_bounds__(256) void expz_kernel()
{
    const int row = blockIdx.x, tid = threadIdx.x;
    const int wid = tid >> 5, lane = tid & 31;
    uint4* srow = (uint4*)(g_Sh + (size_t)row * SEQ);
    uint4 d0 = srow[tid], d1 = srow[tid + 256];
    float f[16];
    {
        const uint32_t* u0 = (const uint32_t*)&d0;
        const uint32_t* u1 = (const uint32_t*)&d1;
#pragma unroll
        for (int i = 0; i < 4; ++i) {
            float2 a = __bfloat1622float2(*(__nv_bfloat162*)&u0[i]);
            f[2 * i] = a.x; f[2 * i + 1] = a.y;
            float2 c = __bfloat1622float2(*(__nv_bfloat162*)&u1[i]);
            f[8 + 2 * i] = c.x; f[9 + 2 * i] = c.y;
        }
    }
    float sum = 0.f, ss = 0.f;
#pragma unroll
    for (int i = 0; i < 16; ++i) { sum += f[i]; ss = fmaf(f[i], f[i], ss); }
#pragma unroll
    for (int o = 16; o > 0; o >>= 1) {
        sum += __shfl_xor_sync(~0u, sum, o);
        ss  += __shfl_xor_sync(~0u, ss, o);
    }
    __shared__ float sA[8], sB[8], sbc[2];
    if (lane == 0) { sA[wid] = sum; sB[wid] = ss; }
    __syncthreads();
    if (tid == 0) {
        float s = 0.f, q = 0.f;
#pragma unroll
        for (int i = 0; i < 8; ++i) { s += sA[i]; q += sB[i]; }
        float mu = s * (1.f / SEQ);
        float var = q * (1.f / SEQ) - mu * mu;
        float c = rsqrtf(var + 1e-5f) * 0.0625f;
        sbc[0] = c; sbc[1] = mu * c;
    }
    __syncthreads();
    const float c = sbc[0], mc = sbc[1];
    float z = 0.f;
#pragma unroll
    for (int i = 0; i < 16; ++i) {
        float e = __expf(fmaf(f[i], c, -mc));
        f[i] = e; z += e;
    }
#pragma unroll
    for (int o = 16; o > 0; o >>= 1) z += __shfl_xor_sync(~0u, z, o);
    if (lane == 0) sA[wid] = z;
    uint4 o0, o1;
    {
        uint32_t* u0 = (uint32_t*)&o0;
        uint32_t* u1 = (uint32_t*)&o1;
#pragma unroll
        for (int i = 0; i < 4; ++i) {
            u0[i] = pack_bf2(f[2 * i], f[2 * i + 1]);
            u1[i] = pack_bf2(f[8 + 2 * i], f[9 + 2 * i]);
        }
    }
    srow[tid] = o0; srow[tid + 256] = o1;
    __syncthreads();
    if (tid == 0) {
        float zt = 0.f;
#pragma unroll
        for (int i = 0; i < 8; ++i) zt += sA[i];
        g_invZ[row] = 1.f / zt;
    }
}

// ======================= K5: O = (P V) * invZ (bf16 HMMA, 3-stage pipeline) ==============
__global__ __launch_bounds__(256, 2) void pv_mma_kernel()
{
    extern __shared__ __align__(16) char sm[];
    const uint32_t base = smem_u32(sm);
    const int tid = threadIdx.x, lane = tid & 31, wid = tid >> 5;
    const int b = blockIdx.z, row0 = blockIdx.y * 128, col0 = blockIdx.x * 128;
    const int m0b = (wid & 3) * 32, n0b = (wid >> 2) * 64;

    float acc[2][8][4];
#pragma unroll
    for (int i = 0; i < 2; ++i)
#pragma unroll
        for (int j = 0; j < 8; ++j)
#pragma unroll
            for (int t = 0; t < 4; ++t) acc[i][j][t] = 0.f;

    gemm_pipe<64>(g_Sh + (size_t)b * SEQ * SEQ + (size_t)row0 * SEQ, SEQ,
                  g_vt + ((size_t)b * CH + col0) * SEQ, SEQ,
                  base, sm, tid, m0b, n0b, lane, acc);

#pragma unroll
    for (int i = 0; i < 2; ++i) {
        const int rl = m0b + i * 16 + (lane >> 2);
        const float izA = g_invZ[b * SEQ + row0 + rl];
        const float izB = g_invZ[b * SEQ + row0 + rl + 8];
#pragma unroll
        for (int j = 0; j < 8; ++j) {
            const int c = col0 + n0b + j * 8 + (lane & 3) * 2;
            float2 oA = make_float2(acc[i][j][0] * izA, acc[i][j][1] * izA);
            float2 oB = make_float2(acc[i][j][2] * izB, acc[i][j][3] * izB);
            *(float2*)(g_o + (size_t)(b * SEQ + row0 + rl) * CH + c)     = oA;
            *(float2*)(g_o + (size_t)(b * SEQ + row0 + rl + 8) * CH + c) = oB;
        }
    }
}

// ======================= K6: out = (query + O) @ Wm^T + bm (bf16x3 HMMA) =======================
__global__ __launch_bounds__(256) void final_mma_kernel(
    const float* __restrict__ query, const float* __restrict__ Wm,
    const float* __restrict__ bm, float* __restrict__ out)
{
    extern __shared__ __align__(16) char sm[];
    const uint32_t base = smem_u32(sm);
    const uint32_t sAhi = base, sAlo = base + STG, sBhi = base + 2 * STG, sBlo = base + 3 * STG;
    const int tid = threadIdx.x, lane = tid & 31, wid = tid >> 5;
    const int row0 = blockIdx.y * 128, col0 = blockIdx.x * 128;
    const int m0b = (wid & 3) * 32, n0b = (wid >> 2) * 64;

    float acc[2][8][4];
#pragma unroll
    for (int i = 0; i < 2; ++i)
#pragma unroll
        for (int j = 0; j < 8; ++j)
#pragma unroll
            for (int t = 0; t < 4; ++t) acc[i][j][t] = 0.f;

    for (int ch = 0; ch < 4; ++ch) {
        const int k0 = ch * 64;
        __syncthreads();
#pragma unroll
        for (int j = 0; j < 4; ++j) {
            int idx = tid + 256 * j;
            int r = idx >> 3, s = idx & 7;
            const float* qa = query + (size_t)(row0 + r) * CH + k0 + s * 8;
            const float* oa = g_o   + (size_t)(row0 + r) * CH + k0 + s * 8;
            float av[8];
            *(float4*)&av[0] = *(const float4*)qa;
            *(float4*)&av[4] = *(const float4*)(qa + 4);
            float4 o0 = *(const float4*)oa, o1 = *(const float4*)(oa + 4);
            av[0] += o0.x; av[1] += o0.y; av[2] += o0.z; av[3] += o0.w;
            av[4] += o1.x; av[5] += o1.y; av[6] += o1.z; av[7] += o1.w;
            uint4 hi, lo;
            uint32_t* hp = (uint32_t*)&hi; uint32_t* lp = (uint32_t*)&lo;
#pragma unroll
            for (int t = 0; t < 4; ++t) {
                float a0 = av[2 * t], a1 = av[2 * t + 1];
                __nv_bfloat16 h0 = __float2bfloat16_rn(a0), h1 = __float2bfloat16_rn(a1);
                float l0 = a0 - __bfloat162float(h0), l1 = a1 - __bfloat162float(h1);
                hp[t] = ((uint32_t)*(uint16_t*)&h1 << 16) | *(uint16_t*)&h0;
                lp[t] = pack_bf2(l0, l1);
            }
            const uint32_t doff = (uint32_t)r * LD2 + s * 16;
            *(uint4*)(sm + doff)        = hi;
            *(uint4*)(sm + STG + doff)  = lo;

            const float* wa = Wm + (size_t)(col0 + r) * CH + k0 + s * 8;
            float wv[8];
            *(float4*)&wv[0] = *(const float4*)wa;
            *(float4*)&wv[4] = *(const float4*)(wa + 4);
#pragma unroll
            for (int t = 0; t < 4; ++t) {
                float a0 = wv[2 * t], a1 = wv[2 * t + 1];
                __nv_bfloat16 h0 = __float2bfloat16_rn(a0), h1 = __float2bfloat16_rn(a1);
                float l0 = a0 - __bfloat162float(h0), l1 = a1 - __bfloat162float(h1);
                hp[t] = ((uint32_t)*(uint16_t*)&h1 << 16) | *(uint16_t*)&h0;
                lp[t] = pack_bf2(l0, l1);
            }
            *(uint4*)(sm + 2 * STG + doff) = hi;
            *(uint4*)(sm + 3 * STG + doff) = lo;
        }
        __syncthreads();

#pragma unroll
        for (int ks = 0; ks < 4; ++ks) {
            const int kb = ks * 32;
            uint32_t ah[2][4], al[2][4];
#pragma unroll
            for (int i = 0; i < 2; ++i) {
                const uint32_t ao = (uint32_t)(m0b + i * 16 + (lane & 15)) * LD2 + kb + ((lane >> 4) << 4);
                ldm_x4(ah[i], sAhi + ao);
                ldm_x4(al[i], sAlo + ao);
            }
            uint32_t bh[4][4], bl[4][4];
#pragma unroll
            for (int p = 0; p < 4; ++p) {
                const uint32_t bo = (uint32_t)(n0b + p * 16 + ((lane >> 4) << 3) + (lane & 7)) * LD2
                                    + kb + (((lane >> 3) & 1) << 4);
                ldm_x4(bh[p], sBhi + bo);
                ldm_x4(bl[p], sBlo + bo);
            }
#pragma unroll
            for (int i = 0; i < 2; ++i)
#pragma unroll
                for (int j = 0; j < 8; ++j) {
                    uint32_t bh0 = bh[j >> 1][(j & 1) * 2], bh1 = bh[j >> 1][(j & 1) * 2 + 1];
                    uint32_t bl0 = bl[j >> 1][(j & 1) * 2], bl1 = bl[j >> 1][(j & 1) * 2 + 1];
                    mma_bf16(acc[i][j], ah[i], bh0, bh1);
                    mma_bf16(acc[i][j], ah[i], bl0, bl1);
                    mma_bf16(acc[i][j], al[i], bh0, bh1);
                }
        }
    }

#pragma unroll
    for (int i = 0; i < 2; ++i) {
        const int r = row0 + m0b + i * 16 + (lane >> 2);
#pragma unroll
        for (int j = 0; j < 8; ++j) {
            const int c = col0 + n0b + j * 8 + (lane & 3) * 2;
            float2 bv2 = *(const float2*)(bm + c);
            *(float2*)(out + (size_t)r * CH + c) =
                make_float2(acc[i][j][0] + bv2.x, acc[i][j][1] + bv2.y);
            *(float2*)(out + (size_t)(r + 8) * CH + c) =
                make_float2(acc[i][j][2] + bv2.x, acc[i][j][3] + bv2.y);
        }
    }
}

extern "C" void kernel_launch(void* const* d_in, const int* in_sizes, int n_in,
                              void* d_out, int out_size)
{
    const float* query = (const float*)d_in[0];
    const float* key   = (const float*)d_in[1];
    const float* value = (const float*)d_in[2];
    const float* Wq    = (const float*)d_in[3];
    const float* bq    = (const float*)d_in[4];
    const float* Wk    = (const float*)d_in[5];
    const float* bk    = (const float*)d_in[6];
    const float* Wv    = (const float*)d_in[7];
    const float* bv    = (const float*)d_in[8];
    const float* Wm    = (const float*)d_in[9];
    const float* bm    = (const float*)d_in[10];
    float* out = (float*)d_out;

    cudaFuncSetAttribute(proj_mma_kernel,  cudaFuncAttributeMaxDynamicSharedMemorySize, DS1);
    cudaFuncSetAttribute(qk_mma_kernel,    cudaFuncAttributeMaxDynamicSharedMemorySize, DS3);
    cudaFuncSetAttribute(pv_mma_kernel,    cudaFuncAttributeMaxDynamicSharedMemorySize, DS3);
    cudaFuncSetAttribute(final_mma_kernel, cudaFuncAttributeMaxDynamicSharedMemorySize, 4 * STG);

    proj_mma_kernel<<<dim3(2, 128, 3), 256, DS1>>>(query, key, value, Wq, bq, Wk, bk, Wv, bv);
    vt_kernel<<<dim3(64, 4, 4), 256>>>();
    qk_mma_kernel<<<dim3(32, 32, 4), 256, DS3>>>();
    expz_kernel<<<ROWS, 256>>>();
    pv_mma_kernel<<<dim3(2, 32, 4), 256, DS3>>>();
    final_mma_kernel<<<dim3(2, 128), 256, 4 * STG>>>(query, Wm, bm, out);
}